// round 17
// baseline (speedup 1.0000x reference)
#include <cuda_runtime.h>
#include <cuda_fp16.h>
#include <cstdint>

#define NMAX 50000
#define EMAX 800000

// ---------------- scratch ----------------
__device__ __half g_embh[(size_t)NMAX * 128];  // fp16 gathered embeddings
__device__ __half g_ah[(size_t)NMAX * 128];    // layer-1 agg output, fp16
__device__ __half g_h2h[(size_t)NMAX * 128];   // layer-2 transformed, fp16
__device__ float g_dinv[NMAX];
__device__ int   g_cnt[NMAX];
__device__ int   g_rowptr[NMAX + 1];
__device__ int   g_fill[NMAX];
__device__ int2  g_cols[EMAX];                 // {src, dinv[src] bits}
__device__ int   g_bsum[64];
__device__ int   g_bflag[64];                  // [0..48] scan flags, [56..59] grid barriers

__device__ __forceinline__ uint32_t h2pack(__half a, __half b) {
    return (uint32_t)__half_as_ushort(a) | ((uint32_t)__half_as_ushort(b) << 16);
}
__device__ __forceinline__ float4 h4unpack(uint2 v) {
    __half2 a = *(__half2*)&v.x, b = *(__half2*)&v.y;
    float2 fa = __half22float2(a), fb = __half22float2(b);
    return make_float4(fa.x, fa.y, fb.x, fb.y);
}

// grid-wide barrier (all blocks resident; distinct counter per use)
__device__ __forceinline__ void gbar(int idx, int expect) {
    __syncthreads();
    if (threadIdx.x == 0) {
        __threadfence();
        atomicAdd(&g_bflag[idx], 1);
        while (((volatile int*)g_bflag)[idx] < expect) { }
    }
    __syncthreads();
}

// ============ PREP: embed-cvt + histogram -> scan -> fill -> agg0, one kernel ============
__global__ void __launch_bounds__(1024, 1)
k_prep(const int* __restrict__ dst, const int* __restrict__ src,
       const int* __restrict__ x_ids, const float4* __restrict__ embed, int n, int E) {
    __shared__ int sh[1024];
    __shared__ int s_off;
    int tid = threadIdx.x, b = blockIdx.x;
    int gt = b * 1024 + tid;
    int gstride = gridDim.x * 1024;
    int nblocks = (int)gridDim.x;

    // ---- phase A: gathered embed fp32 -> fp16, + degree histogram ----
    for (int i = gt; i < n * 32; i += gstride) {
        int node = i >> 5, lane = i & 31;
        int id = __ldg(x_ids + node);
        float4 v = embed[(size_t)id * 32 + lane];
        uint2 hp;
        hp.x = h2pack(__float2half_rn(v.x), __float2half_rn(v.y));
        hp.y = h2pack(__float2half_rn(v.z), __float2half_rn(v.w));
        ((uint2*)g_embh)[i] = hp;
    }
    for (int i = gt; i < E; i += gstride)
        atomicAdd(&g_cnt[dst[i]], 1);
    gbar(56, nblocks);

    // ---- phase B: exclusive scan ----
    int nb = (n + 1023) / 1024;
    if (b < nb) {
        int i0 = b * 1024 + tid;
        int c = (i0 < n) ? g_cnt[i0] : 0;
        sh[tid] = c;
        __syncthreads();
        for (int off = 1; off < 1024; off <<= 1) {
            int t = (tid >= off) ? sh[tid - off] : 0;
            __syncthreads();
            sh[tid] += t;
            __syncthreads();
        }
        if (tid == 1023) {
            g_bsum[b] = sh[1023];
            __threadfence();
            g_bflag[b] = 1;
        }
        if (tid == 0) {
            int off = 0;
            for (int j = 0; j < b; j++) {
                while (((volatile int*)g_bflag)[j] == 0) { }
                off += ((volatile int*)g_bsum)[j];
            }
            s_off = off;
        }
        __syncthreads();
        if (i0 < n) {
            int incl = sh[tid] + s_off;
            int excl = incl - c;
            g_rowptr[i0] = excl;
            g_fill[i0] = excl;
            g_dinv[i0] = rsqrtf((float)(c + 1));
        }
        if (i0 == 0) g_rowptr[n] = E;
    }
    gbar(57, nblocks);

    // ---- phase C: CSR fill ----
    for (int i = gt; i < E; i += gstride) {
        int s = src[i];
        int d = dst[i];
        int pos = atomicAdd(&g_fill[d], 1);
        g_cols[pos] = make_int2(s, __float_as_int(g_dinv[s]));
    }
    gbar(58, nblocks);

    // ---- phase D: layer-1 aggregation (warp per node, unroll 8 for MLP) ----
    int wtot = (gridDim.x * 1024) >> 5;
    int w0 = gt >> 5, lane = gt & 31;
    const uint2* embh = (const uint2*)g_embh;
    for (int w = w0; w < n; w += wtot) {
        float diw = g_dinv[w];
        float4 sv = h4unpack(embh[(size_t)w * 32 + lane]);
        float4 acc = make_float4(sv.x * diw, sv.y * diw, sv.z * diw, sv.w * diw);
        int s = g_rowptr[w], e = g_rowptr[w + 1];
        for (int p = s; p < e; p += 8) {
            int mm = e - p;
            float dj[8]; uint2 rv[8];
            #pragma unroll
            for (int u = 0; u < 8; u++) {
                bool ok = u < mm;
                int2 c = g_cols[ok ? p + u : p];
                dj[u] = ok ? __int_as_float(c.y) : 0.f;
                rv[u] = embh[(size_t)c.x * 32 + lane];
            }
            #pragma unroll
            for (int u = 0; u < 8; u++) {
                float4 v = h4unpack(rv[u]);
                acc.x = fmaf(v.x, dj[u], acc.x);
                acc.y = fmaf(v.y, dj[u], acc.y);
                acc.z = fmaf(v.z, dj[u], acc.z);
                acc.w = fmaf(v.w, dj[u], acc.w);
            }
        }
        float4 o = make_float4(acc.x * diw, acc.y * diw, acc.z * diw, acc.w * diw);
        uint2 hp;
        hp.x = h2pack(__float2half_rn(o.x), __float2half_rn(o.y));
        hp.y = h2pack(__float2half_rn(o.z), __float2half_rn(o.w));
        *(uint2*)(g_ah + (size_t)w * 128 + lane * 4) = hp;
    }
}

// ======== FUSED double GEMM + layer-2 aggregation (one persistent kernel) ========

__device__ __forceinline__ void mma16816(float& c0, float& c1, float& c2, float& c3,
                                         uint32_t a0, uint32_t a1, uint32_t a2, uint32_t a3,
                                         uint32_t b0, uint32_t b1) {
    asm volatile(
        "mma.sync.aligned.m16n8k16.row.col.f32.f16.f16.f32 "
        "{%0,%1,%2,%3}, {%4,%5,%6,%7}, {%8,%9}, {%0,%1,%2,%3};"
        : "+f"(c0), "+f"(c1), "+f"(c2), "+f"(c3)
        : "r"(a0), "r"(a1), "r"(a2), "r"(a3), "r"(b0), "r"(b1));
}
__device__ __forceinline__ void ldm_x4(uint32_t addr, uint32_t& r0, uint32_t& r1,
                                       uint32_t& r2, uint32_t& r3) {
    asm volatile("ldmatrix.sync.aligned.m8n8.x4.shared.b16 {%0,%1,%2,%3}, [%4];"
                 : "=r"(r0), "=r"(r1), "=r"(r2), "=r"(r3) : "r"(addr));
}
__device__ __forceinline__ uint32_t smem_u32(const void* p) {
    return (uint32_t)__cvta_generic_to_shared(p);
}

#define ST1 136
#define ST2 264
#define ABUF 17408u
__global__ void __launch_bounds__(512, 1)
k_gemm_fused(const float* __restrict__ W1, const float* __restrict__ b1,
             const float* __restrict__ g1, const float* __restrict__ be1,
             const float* __restrict__ W2,
             const float* __restrict__ b2, const float* __restrict__ g2,
             const float* __restrict__ be2, float4* __restrict__ outp, int M)
{
    extern __shared__ char sm[];
    __half* W1h = (__half*)sm;
    __half* W2h = (__half*)(sm + 69632);
    __half* Ah0 = (__half*)(sm + 69632 + 67584);
    __half* X1h = (__half*)(sm + 69632 + 67584 + 2 * ABUF);
    float* s_sum = (float*)(sm + 69632 + 67584 + 2 * ABUF + 33792);
    float* s_sq  = s_sum + 64 * 8;

    int tid = threadIdx.x, lane = tid & 31, wid = tid >> 5;
    int wr = wid & 1;
    int wc = wid >> 1;
    int g = lane >> 2, t = lane & 3;
    int tl = lane >> 3, tr = lane & 7;

    // ---- weight conversion ----
    for (int i = tid; i < 128 * 256; i += 512) {
        int k = i >> 8, n = i & 255;
        W1h[n * ST1 + k] = __float2half_rn(W1[i]);
    }
    for (int i = tid; i < 256 * 128; i += 512) {
        int k = i >> 7, n = i & 127;
        W2h[n * ST2 + k] = __float2half_rn(W2[i]);
    }

    // ---- ldmatrix base addresses ----
    uint32_t a_addr[2];
    #pragma unroll
    for (int rt = 0; rt < 2; rt++) {
        int row = wr * 32 + rt * 16 + tr + 8 * (tl & 1);
        a_addr[rt] = smem_u32(Ah0) + (uint32_t)((row * ST1 + 8 * (tl >> 1)) * 2);
    }
    uint32_t w1_addr[2];
    #pragma unroll
    for (int p = 0; p < 2; p++) {
        int n = wc * 32 + p * 16 + (tl >> 1) * 8 + tr;
        w1_addr[p] = smem_u32(W1h) + (uint32_t)((n * ST1 + 8 * (tl & 1)) * 2);
    }
    uint32_t x1_addr[2];
    #pragma unroll
    for (int rt = 0; rt < 2; rt++) {
        int row = wr * 32 + rt * 16 + tr + 8 * (tl & 1);
        x1_addr[rt] = smem_u32(X1h) + (uint32_t)((row * ST2 + 8 * (tl >> 1)) * 2);
    }
    uint32_t w2_addr;
    {
        int n = wc * 16 + (tl >> 1) * 8 + tr;
        w2_addr = smem_u32(W2h) + (uint32_t)((n * ST2 + 8 * (tl & 1)) * 2);
    }

    // ---- A prefetch ----
    uint4 pf[2];
    const uint4 zero4 = make_uint4(0, 0, 0, 0);
    int m0 = blockIdx.x * 64;
    {
        #pragma unroll
        for (int c = 0; c < 2; c++) {
            int idx = tid + c * 512;
            int r = idx >> 4, c8 = (idx & 15) << 3;
            int row = m0 + r;
            pf[c] = (row < M) ? *(const uint4*)(g_ah + (size_t)row * 128 + c8) : zero4;
        }
    }

    uint32_t buf = 0;
    for (; m0 < M; m0 += gridDim.x * 64) {
        __half* Ab = Ah0 + (buf ? ABUF / 2 : 0);
        #pragma unroll
        for (int c = 0; c < 2; c++) {
            int idx = tid + c * 512;
            int r = idx >> 4, c8 = (idx & 15) << 3;
            *(uint4*)(Ab + r * ST1 + c8) = pf[c];
        }
        int m1 = m0 + gridDim.x * 64;
        if (m1 < M) {
            #pragma unroll
            for (int c = 0; c < 2; c++) {
                int idx = tid + c * 512;
                int r = idx >> 4, c8 = (idx & 15) << 3;
                int row = m1 + r;
                pf[c] = (row < M) ? *(const uint4*)(g_ah + (size_t)row * 128 + c8) : zero4;
            }
        }
        __syncthreads();

        uint32_t aoff = buf ? ABUF : 0u;

        // ================= GEMM1: x1 = A @ W1 =================
        float acc[2][4][4];
        #pragma unroll
        for (int rt = 0; rt < 2; rt++)
            #pragma unroll
            for (int nt = 0; nt < 4; nt++)
                #pragma unroll
                for (int q = 0; q < 4; q++) acc[rt][nt][q] = 0.f;

        #pragma unroll
        for (int kt = 0; kt < 8; kt++) {
            uint32_t koff = (uint32_t)kt * 32u + aoff;
            uint32_t koffw = (uint32_t)kt * 32u;
            uint32_t ah[2][4], wb[2][4];
            #pragma unroll
            for (int rt = 0; rt < 2; rt++)
                ldm_x4(a_addr[rt] + koff, ah[rt][0], ah[rt][1], ah[rt][2], ah[rt][3]);
            #pragma unroll
            for (int p = 0; p < 2; p++)
                ldm_x4(w1_addr[p] + koffw, wb[p][0], wb[p][1], wb[p][2], wb[p][3]);
            #pragma unroll
            for (int nt = 0; nt < 4; nt++) {
                uint32_t b0 = wb[nt >> 1][(nt & 1) * 2];
                uint32_t b1 = wb[nt >> 1][(nt & 1) * 2 + 1];
                #pragma unroll
                for (int rt = 0; rt < 2; rt++) {
                    float* c = acc[rt][nt];
                    mma16816(c[0], c[1], c[2], c[3],
                             ah[rt][0], ah[rt][1], ah[rt][2], ah[rt][3], b0, b1);
                }
            }
        }
        buf ^= 1;

        // ---- epilogue1: bias + ReLU + LayerNorm(256) -> X1 smem (fp16) ----
        #pragma unroll
        for (int rt = 0; rt < 2; rt++) {
            float s0 = 0.f, s1 = 0.f, q0 = 0.f, q1 = 0.f;
            #pragma unroll
            for (int nt = 0; nt < 4; nt++) {
                int c0 = wc * 32 + nt * 8 + 2 * t;
                float b0 = b1[c0], b1v = b1[c0 + 1];
                float* c = acc[rt][nt];
                c[0] = fmaxf(c[0] + b0, 0.f);
                c[1] = fmaxf(c[1] + b1v, 0.f);
                c[2] = fmaxf(c[2] + b0, 0.f);
                c[3] = fmaxf(c[3] + b1v, 0.f);
                s0 += c[0] + c[1]; q0 += c[0] * c[0] + c[1] * c[1];
                s1 += c[2] + c[3]; q1 += c[2] * c[2] + c[3] * c[3];
            }
            #pragma unroll
            for (int off = 1; off <= 2; off <<= 1) {
                s0 += __shfl_xor_sync(0xffffffffu, s0, off);
                q0 += __shfl_xor_sync(0xffffffffu, q0, off);
                s1 += __shfl_xor_sync(0xffffffffu, s1, off);
                q1 += __shfl_xor_sync(0xffffffffu, q1, off);
            }
            if (t == 0) {
                int lr = wr * 32 + rt * 16 + g;
                s_sum[lr * 8 + wc] = s0; s_sq[lr * 8 + wc] = q0;
                s_sum[(lr + 8) * 8 + wc] = s1; s_sq[(lr + 8) * 8 + wc] = q1;
            }
        }
        __syncthreads();
        #pragma unroll
        for (int rt = 0; rt < 2; rt++) {
            int lr0 = wr * 32 + rt * 16 + g;
            float ts0 = 0.f, tq0 = 0.f, ts1 = 0.f, tq1 = 0.f;
            #pragma unroll
            for (int j = 0; j < 8; j += 4) {
                float4 a0 = *(const float4*)(s_sum + lr0 * 8 + j);
                float4 b0v = *(const float4*)(s_sq + lr0 * 8 + j);
                float4 a1 = *(const float4*)(s_sum + (lr0 + 8) * 8 + j);
                float4 b1q = *(const float4*)(s_sq + (lr0 + 8) * 8 + j);
                ts0 += (a0.x + a0.y) + (a0.z + a0.w);
                tq0 += (b0v.x + b0v.y) + (b0v.z + b0v.w);
                ts1 += (a1.x + a1.y) + (a1.z + a1.w);
                tq1 += (b1q.x + b1q.y) + (b1q.z + b1q.w);
            }
            float mu0 = ts0 * (1.f / 256.f);
            float mu1 = ts1 * (1.f / 256.f);
            float v0 = tq0 * (1.f / 256.f) - mu0 * mu0;
            float v1 = tq1 * (1.f / 256.f) - mu1 * mu1;
            float rs0 = rsqrtf(v0 + 1e-5f), rs1 = rsqrtf(v1 + 1e-5f);
            #pragma unroll
            for (int nt = 0; nt < 4; nt++) {
                int c0 = wc * 32 + nt * 8 + 2 * t;
                float ga0 = g1[c0], ga1 = g1[c0 + 1];
                float be0 = be1[c0], be1v = be1[c0 + 1];
                float* c = acc[rt][nt];
                float o0 = (c[0] - mu0) * rs0 * ga0 + be0;
                float o1 = (c[1] - mu0) * rs0 * ga1 + be1v;
                float o2 = (c[2] - mu1) * rs1 * ga0 + be0;
                float o3 = (c[3] - mu1) * rs1 * ga1 + be1v;
                *(uint32_t*)(X1h + lr0 * ST2 + c0) =
                    h2pack(__float2half_rn(o0), __float2half_rn(o1));
                *(uint32_t*)(X1h + (lr0 + 8) * ST2 + c0) =
                    h2pack(__float2half_rn(o2), __float2half_rn(o3));
            }
        }
        __syncthreads();

        // ================= GEMM2: h2 = x1 @ W2 =================
        float acc2[2][2][4];
        #pragma unroll
        for (int rt = 0; rt < 2; rt++)
            #pragma unroll
            for (int nt = 0; nt < 2; nt++)
                #pragma unroll
                for (int q = 0; q < 4; q++) acc2[rt][nt][q] = 0.f;

        #pragma unroll
        for (int kt = 0; kt < 16; kt++) {
            uint32_t koff = (uint32_t)kt * 32u;
            uint32_t xh[2][4], wb2[4];
            #pragma unroll
            for (int rt = 0; rt < 2; rt++)
                ldm_x4(x1_addr[rt] + koff, xh[rt][0], xh[rt][1], xh[rt][2], xh[rt][3]);
            ldm_x4(w2_addr + koff, wb2[0], wb2[1], wb2[2], wb2[3]);
            #pragma unroll
            for (int nt = 0; nt < 2; nt++) {
                uint32_t b0 = wb2[nt * 2], b1v = wb2[nt * 2 + 1];
                #pragma unroll
                for (int rt = 0; rt < 2; rt++) {
                    float* c = acc2[rt][nt];
                    mma16816(c[0], c[1], c[2], c[3],
                             xh[rt][0], xh[rt][1], xh[rt][2], xh[rt][3], b0, b1v);
                }
            }
        }

        // ---- epilogue2: * dinv -> g_h2h (fp16) ----
        #pragma unroll
        for (int rt = 0; rt < 2; rt++) {
            int lr0 = wr * 32 + rt * 16 + g;
            int row0 = m0 + lr0, row1 = row0 + 8;
            float d0 = (row0 < M) ? g_dinv[row0] : 0.f;
            float d1 = (row1 < M) ? g_dinv[row1] : 0.f;
            #pragma unroll
            for (int nt = 0; nt < 2; nt++) {
                int c0 = wc * 16 + nt * 8 + 2 * t;
                float* c = acc2[rt][nt];
                if (row0 < M)
                    *(uint32_t*)(g_h2h + (size_t)row0 * 128 + c0) =
                        h2pack(__float2half_rn(c[0] * d0), __float2half_rn(c[1] * d0));
                if (row1 < M)
                    *(uint32_t*)(g_h2h + (size_t)row1 * 128 + c0) =
                        h2pack(__float2half_rn(c[2] * d1), __float2half_rn(c[3] * d1));
            }
        }
        __syncthreads();
    }

    // ================= layer-2 aggregation + bias + LN (grid-strided) =================
    gbar(59, (int)gridDim.x);   // all g_h2h writes visible

    int wtot = ((int)gridDim.x * 512) >> 5;
    int w0 = (blockIdx.x * 512 + tid) >> 5;
    const uint2* xs = (const uint2*)g_h2h;
    for (int w = w0; w < M; w += wtot) {
        float4 acc = h4unpack(xs[(size_t)w * 32 + lane]);
        int s = g_rowptr[w], e = g_rowptr[w + 1];
        for (int p = s; p < e; p += 8) {
            int mm = e - p;
            float dj[8]; uint2 rv[8];
            #pragma unroll
            for (int u = 0; u < 8; u++) {
                bool ok = u < mm;
                int2 c = g_cols[ok ? p + u : p];
                dj[u] = ok ? 1.f : 0.f;
                rv[u] = xs[(size_t)c.x * 32 + lane];
            }
            #pragma unroll
            for (int u = 0; u < 8; u++) {
                float4 v = h4unpack(rv[u]);
                acc.x = fmaf(v.x, dj[u], acc.x);
                acc.y = fmaf(v.y, dj[u], acc.y);
                acc.z = fmaf(v.z, dj[u], acc.z);
                acc.w = fmaf(v.w, dj[u], acc.w);
            }
        }
        float di = g_dinv[w];
        float4 bb = ((const float4*)b2)[lane];
        float4 y = make_float4(acc.x * di + bb.x, acc.y * di + bb.y,
                               acc.z * di + bb.z, acc.w * di + bb.w);
        float s1 = y.x + y.y + y.z + y.w;
        #pragma unroll
        for (int off = 16; off; off >>= 1) s1 += __shfl_xor_sync(0xffffffffu, s1, off);
        float mu = s1 * (1.0f / 128.0f);
        float dx = y.x - mu, dy = y.y - mu, dz = y.z - mu, dw = y.w - mu;
        float sq = dx * dx + dy * dy + dz * dz + dw * dw;
        #pragma unroll
        for (int off = 16; off; off >>= 1) sq += __shfl_xor_sync(0xffffffffu, sq, off);
        float rstd = rsqrtf(sq * (1.0f / 128.0f) + 1e-5f);
        float4 gg = ((const float4*)g2)[lane];
        float4 bt = ((const float4*)be2)[lane];
        outp[(size_t)w * 32 + lane] = make_float4(dx * rstd * gg.x + bt.x,
                                                  dy * rstd * gg.y + bt.y,
                                                  dz * rstd * gg.z + bt.z,
                                                  dw * rstd * gg.w + bt.w);
    }
}

// ---------------- launch ----------------
extern "C" void kernel_launch(void* const* d_in, const int* in_sizes, int n_in,
                              void* d_out, int out_size) {
    const int*   x_ids = (const int*)d_in[0];
    const int*   ei    = (const int*)d_in[1];
    const float* embed = (const float*)d_in[2];
    const float* W1    = (const float*)d_in[3];
    const float* b1    = (const float*)d_in[4];
    const float* g1    = (const float*)d_in[5];
    const float* be1   = (const float*)d_in[6];
    const float* W2    = (const float*)d_in[7];
    const float* b2    = (const float*)d_in[8];
    const float* g2    = (const float*)d_in[9];
    const float* be2   = (const float*)d_in[10];
    float* out = (float*)d_out;

    int n = in_sizes[0];        // 50000
    int E = in_sizes[1] / 2;    // 800000
    const int* src = ei;
    const int* dst = ei + E;

    const int SMEMSZ = 69632 + 67584 + 2 * 17408 + 33792 + 4096;   // 209920
    cudaFuncSetAttribute((const void*)k_gemm_fused,
                         cudaFuncAttributeMaxDynamicSharedMemorySize, SMEMSZ);

    void* p_cnt = nullptr;  cudaGetSymbolAddress(&p_cnt, g_cnt);
    void* p_flag = nullptr; cudaGetSymbolAddress(&p_flag, g_bflag);
    cudaMemsetAsync(p_cnt, 0, (size_t)n * sizeof(int), 0);
    cudaMemsetAsync(p_flag, 0, 64 * sizeof(int), 0);

    k_prep<<<152, 1024>>>(dst, src, x_ids, (const float4*)embed, n, E);           // kernel 0
    k_gemm_fused<<<152, 512, SMEMSZ>>>(W1, b1, g1, be1, W2,
                                       b2, g2, be2, (float4*)out, n);             // kernel 1
}